// round 16
// baseline (speedup 1.0000x reference)
#include <cuda_runtime.h>
#include <cuda_fp16.h>
#include <cstdint>

// Problem constants (fixed by the dataset)
#define N_NODES 50000
#define N_FEAT  256
#define HIDDEN  256
#define H2      128
#define N_EDGES 800000
#define NB_SCAN ((N_NODES + 255) / 256)   // 196 blocks

// ---------------------------------------------------------------------------
// Scratch (device globals — no cudaMalloc allowed). Features stored fp16.
// g_deg relies on static zero-init for the FIRST launch; k_scan1 re-zeros it
// after reading, keeping the invariant across graph replays.
// ---------------------------------------------------------------------------
__device__ __half g_h1 [N_NODES * HIDDEN];  // x@W1
__device__ __half g_o1 [N_NODES * HIDDEN];  // relu(agg1 + b1)
__device__ __half g_h2 [N_NODES * H2];      // (o1@W2) * dinv[row]  (prescaled)
__device__ __half g_zh [N_NODES * H2];      // agg2 + b2 (decode input)
__device__ float  g_dinv[N_NODES];
__device__ int    g_deg [N_NODES];
__device__ int    g_rowptr[N_NODES + 1];
__device__ int    g_cursor[N_NODES];
__device__ int    g_csrc  [N_EDGES];
__device__ int    g_bsum  [256];
__device__ int    g_is64;

// ---------------------------------------------------------------------------
// Packed f32x2 helpers (Blackwell FFMA2/FADD2 via PTX f32x2 ops)
// ---------------------------------------------------------------------------
__device__ __forceinline__ uint64_t pack2(float x, float y) {
    uint64_t r;
    asm("mov.b64 %0, {%1, %2};" : "=l"(r) : "f"(x), "f"(y));
    return r;
}
__device__ __forceinline__ float2 unpack2(uint64_t v) {
    float2 f;
    asm("mov.b64 {%0, %1}, %2;" : "=f"(f.x), "=f"(f.y) : "l"(v));
    return f;
}
__device__ __forceinline__ void ffma2(uint64_t& acc, uint64_t a, uint64_t b) {
    asm("fma.rn.f32x2 %0, %1, %2, %0;" : "+l"(acc) : "l"(a), "l"(b));
}
__device__ __forceinline__ void fadd2(uint64_t& acc, uint64_t o) {
    asm("add.rn.f32x2 %0, %0, %1;" : "+l"(acc) : "l"(o));
}
__device__ __forceinline__ uint64_t h2f2(uint32_t h) {
    float2 f = __half22float2(*(const __half2*)&h);
    return pack2(f.x, f.y);
}

// Load an index from a possibly-int64 array.
__device__ __forceinline__ int ld_idx(const void* arr, int i) {
    if (g_is64) return (int)((const long long*)arr)[i];
    return ((const int*)arr)[i];
}

// ---------------------------------------------------------------------------
// Index dtype detection (one block). Max word idx 2*511*1559+1 < 2E.
// ---------------------------------------------------------------------------
__global__ void k_detect(const unsigned int* __restrict__ raw) {
    __shared__ unsigned int sh;
    if (threadIdx.x == 0) sh = 0u;
    __syncthreads();
    unsigned int acc = 0;
    for (int j = threadIdx.x; j < 512; j += blockDim.x)
        acc |= raw[2 * (j * 1559) + 1];
    atomicOr(&sh, acc);
    __syncthreads();
    if (threadIdx.x == 0) g_is64 = (sh == 0u) ? 1 : 0;
}

// Histogram dst degrees (2 edges/thread, split halves).
__global__ void k_deg_hist(const void* __restrict__ trR, int* __restrict__ deg) {
    int t = blockIdx.x * blockDim.x + threadIdx.x;
    const int H = N_EDGES / 2;
    if (t >= H) return;
    int d0 = ld_idx(trR, N_EDGES + t);
    int d1 = ld_idx(trR, N_EDGES + t + H);
    atomicAdd(&deg[d0], 1);
    atomicAdd(&deg[d1], 1);
}

// ---------------------------------------------------------------------------
// Parallel prefix scan helpers
// ---------------------------------------------------------------------------
__device__ __forceinline__ int blk_scan_excl(int v, int* total) {
    int lane = threadIdx.x & 31;
    int w    = threadIdx.x >> 5;
    int x = v;
#pragma unroll
    for (int o = 1; o < 32; o <<= 1) {
        int y = __shfl_up_sync(0xFFFFFFFFu, x, o);
        if (lane >= o) x += y;
    }
    __shared__ int ws[8];
    if (lane == 31) ws[w] = x;
    __syncthreads();
    if (threadIdx.x < 8) {
        int y = ws[threadIdx.x];
#pragma unroll
        for (int o = 1; o < 8; o <<= 1) {
            int z = __shfl_up_sync(0xFFu, y, o);
            if ((int)threadIdx.x >= o) y += z;
        }
        ws[threadIdx.x] = y;
    }
    __syncthreads();
    int incl = x + (w > 0 ? ws[w - 1] : 0);
    *total = ws[7];
    __syncthreads();
    return incl - v;
}

// Pass 1: per-block exclusive scan of deg + dinv; re-zeros deg for next launch.
__global__ __launch_bounds__(256) void k_scan1(int* __restrict__ deg,
                                               int* __restrict__ rowptr,
                                               float* __restrict__ dinv,
                                               int* __restrict__ bsum) {
    int i = blockIdx.x * 256 + threadIdx.x;
    int v = 0;
    if (i < N_NODES) {
        v = deg[i];
        deg[i] = 0;                              // maintain zero invariant
        dinv[i] = rsqrtf((float)(v + 1));        // +1 self-loop
    }
    int tot;
    int ex = blk_scan_excl(v, &tot);
    if (i < N_NODES) rowptr[i] = ex;
    if (threadIdx.x == 0) bsum[blockIdx.x] = tot;
}

// Pass 2: every block scans the block sums redundantly, adds its offset.
__global__ __launch_bounds__(256) void k_scan2(const int* __restrict__ bsum,
                                               int* __restrict__ rowptr,
                                               int* __restrict__ cursor) {
    int t = threadIdx.x;
    int v = (t < NB_SCAN) ? bsum[t] : 0;
    int tot;
    int ex = blk_scan_excl(v, &tot);
    __shared__ int sb[256];
    sb[t] = ex;
    __syncthreads();
    int off = sb[blockIdx.x];
    int i = blockIdx.x * 256 + t;
    if (i < N_NODES) {
        int r = rowptr[i] + off;
        rowptr[i] = r;
        cursor[i] = r;
    }
    if (blockIdx.x == 0 && t == 0) rowptr[N_NODES] = tot;
}

// Scatter CSR src indices (2 edges/thread, split halves).
__global__ void k_scatter(const void* __restrict__ trR, int* __restrict__ cursor,
                          int* __restrict__ csrc) {
    int t = blockIdx.x * blockDim.x + threadIdx.x;
    const int H = N_EDGES / 2;
    if (t >= H) return;
    int s0 = ld_idx(trR, t);
    int d0 = ld_idx(trR, N_EDGES + t);
    int s1 = ld_idx(trR, t + H);
    int d1 = ld_idx(trR, N_EDGES + t + H);
    int p0 = atomicAdd(&cursor[d0], 1);
    int p1 = atomicAdd(&cursor[d1], 1);
    csrc[p0] = s0;
    csrc[p1] = s1;
}

// ---------------------------------------------------------------------------
// fp16 tensor-core GEMM (mma.sync.m16n8k16), fp16 output, optional per-row
// output scaling. BM=BN=128, BK=16, 256 threads, smem stride 24 halves.
// ---------------------------------------------------------------------------
#define GBM 128
#define GBN 128
#define GBK 16
#define SH  24    // smem stride in halves

__device__ __forceinline__ void mma_f16(float* c, const uint32_t* a, const uint32_t* b) {
    asm volatile(
        "mma.sync.aligned.m16n8k16.row.col.f32.f16.f16.f32 "
        "{%0,%1,%2,%3}, {%4,%5,%6,%7}, {%8,%9}, {%0,%1,%2,%3};"
        : "+f"(c[0]), "+f"(c[1]), "+f"(c[2]), "+f"(c[3])
        : "r"(a[0]), "r"(a[1]), "r"(a[2]), "r"(a[3]), "r"(b[0]), "r"(b[1]));
}

template <bool AHALF, bool SCALE>
__global__ __launch_bounds__(256) void gemm_h16(int M, int N, int K,
                                                const void* __restrict__ Av,
                                                const float* __restrict__ B,
                                                const float* __restrict__ rowscale,
                                                __half* __restrict__ C) {
    __shared__ __half As[GBM][SH];
    __shared__ __half Bs[GBN][SH];

    const int tid  = threadIdx.x;
    const int wid  = tid >> 5;
    const int lane = tid & 31;
    const int grp  = lane >> 2;
    const int tig  = lane & 3;

    const int wrow = (wid & 1) * 64;
    const int wcol = (wid >> 1) * 32;

    const int rowBlk = blockIdx.y * GBM;
    const int colBlk = blockIdx.x * GBN;

    const int am = tid >> 1;
    const int ak = (tid & 1) * 8;
    const int bc = tid & 127;
    const int bk = (tid >> 7) * 8;

    float acc[4][4][4];
#pragma unroll
    for (int i = 0; i < 4; i++)
#pragma unroll
        for (int j = 0; j < 4; j++)
#pragma unroll
            for (int t = 0; t < 4; t++) acc[i][j][t] = 0.f;

    for (int k0 = 0; k0 < K; k0 += GBK) {
        {
            int gr = rowBlk + am;
            if (AHALF) {
                const __half* A = (const __half*)Av;
                uint4 u = make_uint4(0u, 0u, 0u, 0u);
                if (gr < M) u = *(const uint4*)&A[(size_t)gr * K + k0 + ak];
                *(uint4*)&As[am][ak] = u;
            } else {
                const float* A = (const float*)Av;
                float4 v0 = make_float4(0.f, 0.f, 0.f, 0.f);
                float4 v1 = make_float4(0.f, 0.f, 0.f, 0.f);
                if (gr < M) {
                    v0 = *(const float4*)&A[(size_t)gr * K + k0 + ak];
                    v1 = *(const float4*)&A[(size_t)gr * K + k0 + ak + 4];
                }
                __half2 h0 = __floats2half2_rn(v0.x, v0.y);
                __half2 h1 = __floats2half2_rn(v0.z, v0.w);
                __half2 h2 = __floats2half2_rn(v1.x, v1.y);
                __half2 h3 = __floats2half2_rn(v1.z, v1.w);
                uint4 u;
                u.x = *(uint32_t*)&h0; u.y = *(uint32_t*)&h1;
                u.z = *(uint32_t*)&h2; u.w = *(uint32_t*)&h3;
                *(uint4*)&As[am][ak] = u;
            }
        }
        {
            float f[8];
#pragma unroll
            for (int j = 0; j < 8; j++)
                f[j] = B[(size_t)(k0 + bk + j) * N + colBlk + bc];
            __half2 h0 = __floats2half2_rn(f[0], f[1]);
            __half2 h1 = __floats2half2_rn(f[2], f[3]);
            __half2 h2 = __floats2half2_rn(f[4], f[5]);
            __half2 h3 = __floats2half2_rn(f[6], f[7]);
            uint4 u;
            u.x = *(uint32_t*)&h0; u.y = *(uint32_t*)&h1;
            u.z = *(uint32_t*)&h2; u.w = *(uint32_t*)&h3;
            *(uint4*)&Bs[bc][bk] = u;
        }
        __syncthreads();

        uint32_t afr[4][4];
        uint32_t bfr[4][2];
#pragma unroll
        for (int i = 0; i < 4; i++) {
            int r = wrow + i * 16;
            afr[i][0] = *(const uint32_t*)&As[r + grp    ][2 * tig    ];
            afr[i][1] = *(const uint32_t*)&As[r + grp + 8][2 * tig    ];
            afr[i][2] = *(const uint32_t*)&As[r + grp    ][2 * tig + 8];
            afr[i][3] = *(const uint32_t*)&As[r + grp + 8][2 * tig + 8];
        }
#pragma unroll
        for (int j = 0; j < 4; j++) {
            int c = wcol + j * 8;
            bfr[j][0] = *(const uint32_t*)&Bs[c + grp][2 * tig    ];
            bfr[j][1] = *(const uint32_t*)&Bs[c + grp][2 * tig + 8];
        }
#pragma unroll
        for (int i = 0; i < 4; i++)
#pragma unroll
            for (int j = 0; j < 4; j++)
                mma_f16(acc[i][j], afr[i], bfr[j]);
        __syncthreads();
    }

#pragma unroll
    for (int i = 0; i < 4; i++) {
        int r0 = rowBlk + wrow + i * 16 + grp;
        float s0 = 1.f, s1 = 1.f;
        if (SCALE) {
            if (r0 < M)     s0 = rowscale[r0];
            if (r0 + 8 < M) s1 = rowscale[r0 + 8];
        }
#pragma unroll
        for (int j = 0; j < 4; j++) {
            int c = colBlk + wcol + j * 8 + 2 * tig;
            if (r0 < M) {
                __half2 p = __floats2half2_rn(acc[i][j][0] * s0, acc[i][j][1] * s0);
                *(uint32_t*)&C[(size_t)r0 * N + c] = *(uint32_t*)&p;
            }
            if (r0 + 8 < M) {
                __half2 p = __floats2half2_rn(acc[i][j][2] * s1, acc[i][j][3] * s1);
                *(uint32_t*)&C[(size_t)(r0 + 8) * N + c] = *(uint32_t*)&p;
            }
        }
    }
}

// ---------------------------------------------------------------------------
// fp16 gather helpers (packed f32x2 accumulation)
// ---------------------------------------------------------------------------
__device__ __forceinline__ void hfma8p(uint4 u, uint64_t nn, uint64_t* acc) {
    ffma2(acc[0], h2f2(u.x), nn);
    ffma2(acc[1], h2f2(u.y), nn);
    ffma2(acc[2], h2f2(u.z), nn);
    ffma2(acc[3], h2f2(u.w), nn);
}
__device__ __forceinline__ void hadd4p(uint2 u, uint64_t* acc) {
    fadd2(acc[0], h2f2(u.x));
    fadd2(acc[1], h2f2(u.y));
}

// ---------------------------------------------------------------------------
// CSR aggregation C=256: TWO warps per node (pair in same block). Odd warp
// handles the upper half of the neighbor list, spills to smem; even warp
// combines + self term + bias + relu. 4 nodes per 256-thread block;
// N_NODES divisible by 4 so every block is full.
// ---------------------------------------------------------------------------
__global__ __launch_bounds__(256) void k_agg256(const int* __restrict__ rowptr,
                                                const int* __restrict__ csrc,
                                                const __half* __restrict__ h,
                                                const float* __restrict__ dinv,
                                                const float* __restrict__ bias,
                                                __half* __restrict__ out) {
    __shared__ float red[4][256];    // [pair][t*32+lane]

    int gtid = blockIdx.x * 256 + threadIdx.x;
    int w    = gtid >> 5;
    int node = w >> 1;
    int half = w & 1;
    int lane = gtid & 31;
    int pair = (threadIdx.x >> 5) >> 1;   // 0..3

    const uint4* hp = (const uint4*)h;

    float di = dinv[node];
    uint64_t acc[4] = {0, 0, 0, 0};

    int beg = rowptr[node];
    int end = rowptr[node + 1];
    int mid = beg + ((end - beg) >> 1);
    int lo  = half ? mid : beg;
    int hi  = half ? end : mid;

    if (!half)   // self-loop term handled by even warp
        hfma8p(__ldg(&hp[(size_t)node * 32 + lane]), pack2(di * di, di * di), acc);

    int p = lo;
    for (; p + 4 <= hi; p += 4) {
        int s0 = __ldg(&csrc[p]);
        int s1 = __ldg(&csrc[p + 1]);
        int s2 = __ldg(&csrc[p + 2]);
        int s3 = __ldg(&csrc[p + 3]);
        float n0 = di * __ldg(&dinv[s0]);
        float n1 = di * __ldg(&dinv[s1]);
        float n2 = di * __ldg(&dinv[s2]);
        float n3 = di * __ldg(&dinv[s3]);
        uint4 u0 = __ldg(&hp[(size_t)s0 * 32 + lane]);
        uint4 u1 = __ldg(&hp[(size_t)s1 * 32 + lane]);
        uint4 u2 = __ldg(&hp[(size_t)s2 * 32 + lane]);
        uint4 u3 = __ldg(&hp[(size_t)s3 * 32 + lane]);
        hfma8p(u0, pack2(n0, n0), acc);
        hfma8p(u1, pack2(n1, n1), acc);
        hfma8p(u2, pack2(n2, n2), acc);
        hfma8p(u3, pack2(n3, n3), acc);
    }
    for (; p < hi; p++) {
        int s0 = __ldg(&csrc[p]);
        float n0 = di * __ldg(&dinv[s0]);
        hfma8p(__ldg(&hp[(size_t)s0 * 32 + lane]), pack2(n0, n0), acc);
    }

    float a[8];
#pragma unroll
    for (int q = 0; q < 4; q++) {
        float2 f = unpack2(acc[q]);
        a[2 * q] = f.x; a[2 * q + 1] = f.y;
    }

    if (half) {
#pragma unroll
        for (int t = 0; t < 8; t++) red[pair][t * 32 + lane] = a[t];
    }
    __syncthreads();
    if (!half) {
        int c = lane * 8;
#pragma unroll
        for (int t = 0; t < 8; t++) {
            a[t] += red[pair][t * 32 + lane];
            a[t] += __ldg(&bias[c + t]);
            a[t] = fmaxf(a[t], 0.f);
        }
        __half2 p0 = __floats2half2_rn(a[0], a[1]);
        __half2 p1 = __floats2half2_rn(a[2], a[3]);
        __half2 p2 = __floats2half2_rn(a[4], a[5]);
        __half2 p3 = __floats2half2_rn(a[6], a[7]);
        uint4 o;
        o.x = *(uint32_t*)&p0; o.y = *(uint32_t*)&p1;
        o.z = *(uint32_t*)&p2; o.w = *(uint32_t*)&p3;
        ((uint4*)out)[(size_t)node * 32 + lane] = o;
    }
}

// ---------------------------------------------------------------------------
// CSR aggregation C=128 over PRESCALED rows (h' = h*dinv), two warps/node:
//   out[d] = dinv[d] * (h'[d] + sum_s h'[s]) + b2
// ---------------------------------------------------------------------------
__global__ __launch_bounds__(256) void k_agg128s(const int* __restrict__ rowptr,
                                                 const int* __restrict__ csrc,
                                                 const __half* __restrict__ h,
                                                 const float* __restrict__ dinv,
                                                 const float* __restrict__ bias,
                                                 __half* __restrict__ out) {
    __shared__ float red[4][128];    // [pair][t*32+lane]

    int gtid = blockIdx.x * 256 + threadIdx.x;
    int w    = gtid >> 5;
    int node = w >> 1;
    int half = w & 1;
    int lane = gtid & 31;
    int pair = (threadIdx.x >> 5) >> 1;

    const uint2* hp = (const uint2*)h;

    uint64_t acc[2] = {0, 0};

    int beg = rowptr[node];
    int end = rowptr[node + 1];
    int mid = beg + ((end - beg) >> 1);
    int lo  = half ? mid : beg;
    int hi  = half ? end : mid;

    if (!half)
        hadd4p(__ldg(&hp[(size_t)node * 32 + lane]), acc);   // self term h'[d]

    int p = lo;
    for (; p + 4 <= hi; p += 4) {
        int s0 = __ldg(&csrc[p]);
        int s1 = __ldg(&csrc[p + 1]);
        int s2 = __ldg(&csrc[p + 2]);
        int s3 = __ldg(&csrc[p + 3]);
        uint2 u0 = __ldg(&hp[(size_t)s0 * 32 + lane]);
        uint2 u1 = __ldg(&hp[(size_t)s1 * 32 + lane]);
        uint2 u2 = __ldg(&hp[(size_t)s2 * 32 + lane]);
        uint2 u3 = __ldg(&hp[(size_t)s3 * 32 + lane]);
        hadd4p(u0, acc);
        hadd4p(u1, acc);
        hadd4p(u2, acc);
        hadd4p(u3, acc);
    }
    for (; p < hi; p++) {
        int s0 = __ldg(&csrc[p]);
        hadd4p(__ldg(&hp[(size_t)s0 * 32 + lane]), acc);
    }

    float a[4];
    {
        float2 f0 = unpack2(acc[0]);
        float2 f1 = unpack2(acc[1]);
        a[0] = f0.x; a[1] = f0.y; a[2] = f1.x; a[3] = f1.y;
    }

    if (half) {
#pragma unroll
        for (int t = 0; t < 4; t++) red[pair][t * 32 + lane] = a[t];
    }
    __syncthreads();
    if (!half) {
        float di = dinv[node];
        int c = lane * 4;
#pragma unroll
        for (int t = 0; t < 4; t++) {
            a[t] += red[pair][t * 32 + lane];
            a[t] = a[t] * di + __ldg(&bias[c + t]);
        }
        __half2 p0 = __floats2half2_rn(a[0], a[1]);
        __half2 p1 = __floats2half2_rn(a[2], a[3]);
        uint2 o;
        o.x = *(uint32_t*)&p0; o.y = *(uint32_t*)&p1;
        ((uint2*)out)[(size_t)node * 32 + lane] = o;
    }
}

// ---------------------------------------------------------------------------
// Decode: logits[e] = dot(zh[a], zh[b]); one edge per 16-lane half-warp.
// ---------------------------------------------------------------------------
__global__ void k_decode(const void* __restrict__ peR,
                         const void* __restrict__ neR,
                         const __half* __restrict__ zh,
                         float* __restrict__ out) {
    int gtid = blockIdx.x * blockDim.x + threadIdx.x;
    int warp = gtid >> 5;
    int lane = gtid & 31;
    int half_id = lane >> 4;
    int sl = lane & 15;
    int eg = warp * 2 + half_id;
    if (eg >= 2 * N_EDGES) return;
    const void* src = (eg < N_EDGES) ? peR : neR;
    int e = (eg < N_EDGES) ? eg : eg - N_EDGES;
    int a, b;
    if (g_is64) {
        a = (int)((const long long*)src)[e];
        b = (int)((const long long*)src)[N_EDGES + e];
    } else {
        a = ((const int*)src)[e];
        b = ((const int*)src)[N_EDGES + e];
    }
    uint4 ua = __ldg(&((const uint4*)&zh[(size_t)a * H2])[sl]);
    uint4 ub = __ldg(&((const uint4*)&zh[(size_t)b * H2])[sl]);
    uint64_t acc0 = 0, acc1 = 0;
    ffma2(acc0, h2f2(ua.x), h2f2(ub.x));
    ffma2(acc1, h2f2(ua.y), h2f2(ub.y));
    ffma2(acc0, h2f2(ua.z), h2f2(ub.z));
    ffma2(acc1, h2f2(ua.w), h2f2(ub.w));
    float2 r0 = unpack2(acc0);
    float2 r1 = unpack2(acc1);
    float s = (r0.x + r0.y) + (r1.x + r1.y);
#pragma unroll
    for (int o = 8; o; o >>= 1) s += __shfl_xor_sync(0xFFFFFFFFu, s, o);
    if (sl == 0) out[eg] = s;
}

// ---------------------------------------------------------------------------
// Launch — GEMM1 forked onto a side stream to overlap the CSR build.
// ---------------------------------------------------------------------------
extern "C" void kernel_launch(void* const* d_in, const int* in_sizes, int n_in,
                              void* d_out, int out_size) {
    const float* x    = (const float*)d_in[0];
    const void*  trR  = d_in[1];
    const void*  peR  = d_in[2];
    const void*  neR  = d_in[3];
    const float* W1   = (const float*)d_in[4];
    const float* b1   = (const float*)d_in[5];
    const float* W2   = (const float*)d_in[6];
    const float* b2   = (const float*)d_in[7];
    float* out = (float*)d_out;

    __half *h1, *o1, *h2, *zh;
    float *dinv;
    int *deg, *rowptr, *cursor, *csrc, *bsum;
    cudaGetSymbolAddress((void**)&h1,     g_h1);
    cudaGetSymbolAddress((void**)&o1,     g_o1);
    cudaGetSymbolAddress((void**)&h2,     g_h2);
    cudaGetSymbolAddress((void**)&zh,     g_zh);
    cudaGetSymbolAddress((void**)&dinv,   g_dinv);
    cudaGetSymbolAddress((void**)&deg,    g_deg);
    cudaGetSymbolAddress((void**)&rowptr, g_rowptr);
    cudaGetSymbolAddress((void**)&cursor, g_cursor);
    cudaGetSymbolAddress((void**)&csrc,   g_csrc);
    cudaGetSymbolAddress((void**)&bsum,   g_bsum);

    static cudaStream_t s1 = nullptr;
    static cudaEvent_t  e_fork = nullptr, e_g1 = nullptr;
    if (s1 == nullptr) {
        cudaStreamCreateWithFlags(&s1, cudaStreamNonBlocking);
        cudaEventCreateWithFlags(&e_fork, cudaEventDisableTiming);
        cudaEventCreateWithFlags(&e_g1,   cudaEventDisableTiming);
    }

    // Fork GEMM1 (independent of all edge data) onto stream 1.
    cudaEventRecord(e_fork, 0);
    cudaStreamWaitEvent(s1, e_fork, 0);
    {
        dim3 grid(HIDDEN / GBN, (N_NODES + GBM - 1) / GBM);
        gemm_h16<false, false><<<grid, 256, 0, s1>>>(N_NODES, HIDDEN, N_FEAT,
                                                     x, W1, nullptr, h1);
    }
    cudaEventRecord(e_g1, s1);

    // Main: setup + parallel CSR build (deg kept zero across launches by scan1).
    k_detect<<<1, 256>>>((const unsigned int*)trR);
    k_deg_hist<<<(N_EDGES / 2 + 255) / 256, 256>>>(trR, deg);
    k_scan1<<<NB_SCAN, 256>>>(deg, rowptr, dinv, bsum);
    k_scan2<<<NB_SCAN, 256>>>(bsum, rowptr, cursor);
    k_scatter<<<(N_EDGES / 2 + 255) / 256, 256>>>(trR, cursor, csrc);

    // Join: agg1 needs both h1 (side) and CSR (main).
    cudaStreamWaitEvent(0, e_g1, 0);

    // o1 = relu(agg(h1) + b1)   — 2 warps per node
    {
        int blocks = (N_NODES * 2 * 32) / 256;   // 12500
        k_agg256<<<blocks, 256>>>(rowptr, csrc, h1, dinv, b1, o1);
    }

    // h2 = (o1 @ W2) * dinv[row]   (prescaled for agg2)
    {
        dim3 grid(H2 / GBN, (N_NODES + GBM - 1) / GBM);
        gemm_h16<true, true><<<grid, 256>>>(N_NODES, H2, HIDDEN, o1, W2, dinv, h2);
    }

    // zh = dinv[d]*(h2[d] + sum h2[s]) + b2   — 2 warps per node
    {
        int blocks = (N_NODES * 2 * 32) / 256;   // 12500
        k_agg128s<<<blocks, 256>>>(rowptr, csrc, h2, dinv, b2, zh);
    }

    // decode: one edge per half-warp
    {
        long long threads = (long long)N_EDGES * 32;   // 2E * 16
        k_decode<<<(unsigned)((threads + 255) / 256), 256>>>(peR, neR, zh, out);
    }
}

// round 17
// speedup vs baseline: 1.2496x; 1.2496x over previous
#include <cuda_runtime.h>
#include <cuda_fp16.h>
#include <cstdint>

// Problem constants (fixed by the dataset)
#define N_NODES 50000
#define N_FEAT  256
#define HIDDEN  256
#define H2      128
#define N_EDGES 800000
#define NB_SCAN ((N_NODES + 255) / 256)   // 196 blocks

// ---------------------------------------------------------------------------
// Scratch (device globals — no cudaMalloc allowed). Features stored fp16.
// g_deg relies on static zero-init for the FIRST launch; k_scan1 re-zeros it
// after reading, keeping the invariant across graph replays.
// ---------------------------------------------------------------------------
__device__ __half g_h1 [N_NODES * HIDDEN];  // x@W1
__device__ __half g_o1 [N_NODES * HIDDEN];  // relu(agg1 + b1)
__device__ __half g_h2 [N_NODES * H2];      // (o1@W2) * dinv[row]  (prescaled)
__device__ __half g_zh [N_NODES * H2];      // agg2 + b2 (decode input)
__device__ float  g_dinv[N_NODES];
__device__ int    g_deg [N_NODES];
__device__ int    g_rowptr[N_NODES + 1];
__device__ int    g_cursor[N_NODES];
__device__ int    g_csrc  [N_EDGES];
__device__ int    g_bsum  [256];
__device__ int    g_is64;

// ---------------------------------------------------------------------------
// Packed f32x2 helpers (Blackwell FFMA2/FADD2 via PTX f32x2 ops)
// ---------------------------------------------------------------------------
__device__ __forceinline__ uint64_t pack2(float x, float y) {
    uint64_t r;
    asm("mov.b64 %0, {%1, %2};" : "=l"(r) : "f"(x), "f"(y));
    return r;
}
__device__ __forceinline__ float2 unpack2(uint64_t v) {
    float2 f;
    asm("mov.b64 {%0, %1}, %2;" : "=f"(f.x), "=f"(f.y) : "l"(v));
    return f;
}
__device__ __forceinline__ void ffma2(uint64_t& acc, uint64_t a, uint64_t b) {
    asm("fma.rn.f32x2 %0, %1, %2, %0;" : "+l"(acc) : "l"(a), "l"(b));
}
__device__ __forceinline__ void fadd2(uint64_t& acc, uint64_t o) {
    asm("add.rn.f32x2 %0, %0, %1;" : "+l"(acc) : "l"(o));
}
__device__ __forceinline__ uint64_t h2f2(uint32_t h) {
    float2 f = __half22float2(*(const __half2*)&h);
    return pack2(f.x, f.y);
}

// Load an index from a possibly-int64 array.
__device__ __forceinline__ int ld_idx(const void* arr, int i) {
    if (g_is64) return (int)((const long long*)arr)[i];
    return ((const int*)arr)[i];
}

// ---------------------------------------------------------------------------
// Index dtype detection (one block). Max word idx 2*511*1559+1 < 2E.
// ---------------------------------------------------------------------------
__global__ void k_detect(const unsigned int* __restrict__ raw) {
    __shared__ unsigned int sh;
    if (threadIdx.x == 0) sh = 0u;
    __syncthreads();
    unsigned int acc = 0;
    for (int j = threadIdx.x; j < 512; j += blockDim.x)
        acc |= raw[2 * (j * 1559) + 1];
    atomicOr(&sh, acc);
    __syncthreads();
    if (threadIdx.x == 0) g_is64 = (sh == 0u) ? 1 : 0;
}

// Histogram dst degrees (2 edges/thread, split halves).
__global__ void k_deg_hist(const void* __restrict__ trR, int* __restrict__ deg) {
    int t = blockIdx.x * blockDim.x + threadIdx.x;
    const int H = N_EDGES / 2;
    if (t >= H) return;
    int d0 = ld_idx(trR, N_EDGES + t);
    int d1 = ld_idx(trR, N_EDGES + t + H);
    atomicAdd(&deg[d0], 1);
    atomicAdd(&deg[d1], 1);
}

// ---------------------------------------------------------------------------
// Parallel prefix scan helpers
// ---------------------------------------------------------------------------
__device__ __forceinline__ int blk_scan_excl(int v, int* total) {
    int lane = threadIdx.x & 31;
    int w    = threadIdx.x >> 5;
    int x = v;
#pragma unroll
    for (int o = 1; o < 32; o <<= 1) {
        int y = __shfl_up_sync(0xFFFFFFFFu, x, o);
        if (lane >= o) x += y;
    }
    __shared__ int ws[8];
    if (lane == 31) ws[w] = x;
    __syncthreads();
    if (threadIdx.x < 8) {
        int y = ws[threadIdx.x];
#pragma unroll
        for (int o = 1; o < 8; o <<= 1) {
            int z = __shfl_up_sync(0xFFu, y, o);
            if ((int)threadIdx.x >= o) y += z;
        }
        ws[threadIdx.x] = y;
    }
    __syncthreads();
    int incl = x + (w > 0 ? ws[w - 1] : 0);
    *total = ws[7];
    __syncthreads();
    return incl - v;
}

// Pass 1: per-block exclusive scan of deg + dinv; re-zeros deg for next launch.
__global__ __launch_bounds__(256) void k_scan1(int* __restrict__ deg,
                                               int* __restrict__ rowptr,
                                               float* __restrict__ dinv,
                                               int* __restrict__ bsum) {
    int i = blockIdx.x * 256 + threadIdx.x;
    int v = 0;
    if (i < N_NODES) {
        v = deg[i];
        deg[i] = 0;                              // maintain zero invariant
        dinv[i] = rsqrtf((float)(v + 1));        // +1 self-loop
    }
    int tot;
    int ex = blk_scan_excl(v, &tot);
    if (i < N_NODES) rowptr[i] = ex;
    if (threadIdx.x == 0) bsum[blockIdx.x] = tot;
}

// Pass 2: every block scans the block sums redundantly, adds its offset.
__global__ __launch_bounds__(256) void k_scan2(const int* __restrict__ bsum,
                                               int* __restrict__ rowptr,
                                               int* __restrict__ cursor) {
    int t = threadIdx.x;
    int v = (t < NB_SCAN) ? bsum[t] : 0;
    int tot;
    int ex = blk_scan_excl(v, &tot);
    __shared__ int sb[256];
    sb[t] = ex;
    __syncthreads();
    int off = sb[blockIdx.x];
    int i = blockIdx.x * 256 + t;
    if (i < N_NODES) {
        int r = rowptr[i] + off;
        rowptr[i] = r;
        cursor[i] = r;
    }
    if (blockIdx.x == 0 && t == 0) rowptr[N_NODES] = tot;
}

// Scatter CSR src indices (2 edges/thread, split halves).
__global__ void k_scatter(const void* __restrict__ trR, int* __restrict__ cursor,
                          int* __restrict__ csrc) {
    int t = blockIdx.x * blockDim.x + threadIdx.x;
    const int H = N_EDGES / 2;
    if (t >= H) return;
    int s0 = ld_idx(trR, t);
    int d0 = ld_idx(trR, N_EDGES + t);
    int s1 = ld_idx(trR, t + H);
    int d1 = ld_idx(trR, N_EDGES + t + H);
    int p0 = atomicAdd(&cursor[d0], 1);
    int p1 = atomicAdd(&cursor[d1], 1);
    csrc[p0] = s0;
    csrc[p1] = s1;
}

// ---------------------------------------------------------------------------
// fp16 tensor-core GEMM (mma.sync.m16n8k16), fp16 output, optional per-row
// output scaling. BM=BN=128, BK=16, 256 threads, smem stride 24 halves.
// ---------------------------------------------------------------------------
#define GBM 128
#define GBN 128
#define GBK 16
#define SH  24    // smem stride in halves

__device__ __forceinline__ void mma_f16(float* c, const uint32_t* a, const uint32_t* b) {
    asm volatile(
        "mma.sync.aligned.m16n8k16.row.col.f32.f16.f16.f32 "
        "{%0,%1,%2,%3}, {%4,%5,%6,%7}, {%8,%9}, {%0,%1,%2,%3};"
        : "+f"(c[0]), "+f"(c[1]), "+f"(c[2]), "+f"(c[3])
        : "r"(a[0]), "r"(a[1]), "r"(a[2]), "r"(a[3]), "r"(b[0]), "r"(b[1]));
}

template <bool AHALF, bool SCALE>
__global__ __launch_bounds__(256) void gemm_h16(int M, int N, int K,
                                                const void* __restrict__ Av,
                                                const float* __restrict__ B,
                                                const float* __restrict__ rowscale,
                                                __half* __restrict__ C) {
    __shared__ __half As[GBM][SH];
    __shared__ __half Bs[GBN][SH];

    const int tid  = threadIdx.x;
    const int wid  = tid >> 5;
    const int lane = tid & 31;
    const int grp  = lane >> 2;
    const int tig  = lane & 3;

    const int wrow = (wid & 1) * 64;
    const int wcol = (wid >> 1) * 32;

    const int rowBlk = blockIdx.y * GBM;
    const int colBlk = blockIdx.x * GBN;

    const int am = tid >> 1;
    const int ak = (tid & 1) * 8;
    const int bc = tid & 127;
    const int bk = (tid >> 7) * 8;

    float acc[4][4][4];
#pragma unroll
    for (int i = 0; i < 4; i++)
#pragma unroll
        for (int j = 0; j < 4; j++)
#pragma unroll
            for (int t = 0; t < 4; t++) acc[i][j][t] = 0.f;

    for (int k0 = 0; k0 < K; k0 += GBK) {
        {
            int gr = rowBlk + am;
            if (AHALF) {
                const __half* A = (const __half*)Av;
                uint4 u = make_uint4(0u, 0u, 0u, 0u);
                if (gr < M) u = *(const uint4*)&A[(size_t)gr * K + k0 + ak];
                *(uint4*)&As[am][ak] = u;
            } else {
                const float* A = (const float*)Av;
                float4 v0 = make_float4(0.f, 0.f, 0.f, 0.f);
                float4 v1 = make_float4(0.f, 0.f, 0.f, 0.f);
                if (gr < M) {
                    v0 = *(const float4*)&A[(size_t)gr * K + k0 + ak];
                    v1 = *(const float4*)&A[(size_t)gr * K + k0 + ak + 4];
                }
                __half2 h0 = __floats2half2_rn(v0.x, v0.y);
                __half2 h1 = __floats2half2_rn(v0.z, v0.w);
                __half2 h2 = __floats2half2_rn(v1.x, v1.y);
                __half2 h3 = __floats2half2_rn(v1.z, v1.w);
                uint4 u;
                u.x = *(uint32_t*)&h0; u.y = *(uint32_t*)&h1;
                u.z = *(uint32_t*)&h2; u.w = *(uint32_t*)&h3;
                *(uint4*)&As[am][ak] = u;
            }
        }
        {
            float f[8];
#pragma unroll
            for (int j = 0; j < 8; j++)
                f[j] = B[(size_t)(k0 + bk + j) * N + colBlk + bc];
            __half2 h0 = __floats2half2_rn(f[0], f[1]);
            __half2 h1 = __floats2half2_rn(f[2], f[3]);
            __half2 h2 = __floats2half2_rn(f[4], f[5]);
            __half2 h3 = __floats2half2_rn(f[6], f[7]);
            uint4 u;
            u.x = *(uint32_t*)&h0; u.y = *(uint32_t*)&h1;
            u.z = *(uint32_t*)&h2; u.w = *(uint32_t*)&h3;
            *(uint4*)&Bs[bc][bk] = u;
        }
        __syncthreads();

        uint32_t afr[4][4];
        uint32_t bfr[4][2];
#pragma unroll
        for (int i = 0; i < 4; i++) {
            int r = wrow + i * 16;
            afr[i][0] = *(const uint32_t*)&As[r + grp    ][2 * tig    ];
            afr[i][1] = *(const uint32_t*)&As[r + grp + 8][2 * tig    ];
            afr[i][2] = *(const uint32_t*)&As[r + grp    ][2 * tig + 8];
            afr[i][3] = *(const uint32_t*)&As[r + grp + 8][2 * tig + 8];
        }
#pragma unroll
        for (int j = 0; j < 4; j++) {
            int c = wcol + j * 8;
            bfr[j][0] = *(const uint32_t*)&Bs[c + grp][2 * tig    ];
            bfr[j][1] = *(const uint32_t*)&Bs[c + grp][2 * tig + 8];
        }
#pragma unroll
        for (int i = 0; i < 4; i++)
#pragma unroll
            for (int j = 0; j < 4; j++)
                mma_f16(acc[i][j], afr[i], bfr[j]);
        __syncthreads();
    }

#pragma unroll
    for (int i = 0; i < 4; i++) {
        int r0 = rowBlk + wrow + i * 16 + grp;
        float s0 = 1.f, s1 = 1.f;
        if (SCALE) {
            if (r0 < M)     s0 = rowscale[r0];
            if (r0 + 8 < M) s1 = rowscale[r0 + 8];
        }
#pragma unroll
        for (int j = 0; j < 4; j++) {
            int c = colBlk + wcol + j * 8 + 2 * tig;
            if (r0 < M) {
                __half2 p = __floats2half2_rn(acc[i][j][0] * s0, acc[i][j][1] * s0);
                *(uint32_t*)&C[(size_t)r0 * N + c] = *(uint32_t*)&p;
            }
            if (r0 + 8 < M) {
                __half2 p = __floats2half2_rn(acc[i][j][2] * s1, acc[i][j][3] * s1);
                *(uint32_t*)&C[(size_t)(r0 + 8) * N + c] = *(uint32_t*)&p;
            }
        }
    }
}

// ---------------------------------------------------------------------------
// fp16 gather helpers (packed f32x2 accumulation)
// ---------------------------------------------------------------------------
__device__ __forceinline__ void hfma8p(uint4 u, uint64_t nn, uint64_t* acc) {
    ffma2(acc[0], h2f2(u.x), nn);
    ffma2(acc[1], h2f2(u.y), nn);
    ffma2(acc[2], h2f2(u.z), nn);
    ffma2(acc[3], h2f2(u.w), nn);
}
__device__ __forceinline__ void hadd4p(uint2 u, uint64_t* acc) {
    fadd2(acc[0], h2f2(u.x));
    fadd2(acc[1], h2f2(u.y));
}

// ---------------------------------------------------------------------------
// CSR aggregation C=256, fp16 in/out, ONE warp per node (measured best),
// fused norm+bias+relu, unroll 8.
// ---------------------------------------------------------------------------
__global__ __launch_bounds__(256) void k_agg256(const int* __restrict__ rowptr,
                                                const int* __restrict__ csrc,
                                                const __half* __restrict__ h,
                                                const float* __restrict__ dinv,
                                                const float* __restrict__ bias,
                                                __half* __restrict__ out) {
    int gtid = blockIdx.x * blockDim.x + threadIdx.x;
    int node = gtid >> 5;
    int lane = gtid & 31;
    if (node >= N_NODES) return;

    const uint4* hp = (const uint4*)h;
    size_t rowq = (size_t)node * 32 + lane;

    float di = dinv[node];
    uint64_t acc[4] = {0, 0, 0, 0};
    hfma8p(__ldg(&hp[rowq]), pack2(di * di, di * di), acc);

    int beg = rowptr[node];
    int end = rowptr[node + 1];
    int p = beg;
    for (; p + 8 <= end; p += 8) {
        int s[8];
        float n[8];
        uint4 u[8];
#pragma unroll
        for (int q = 0; q < 8; q++) s[q] = __ldg(&csrc[p + q]);
#pragma unroll
        for (int q = 0; q < 8; q++) u[q] = __ldg(&hp[(size_t)s[q] * 32 + lane]);
#pragma unroll
        for (int q = 0; q < 8; q++) n[q] = di * __ldg(&dinv[s[q]]);
#pragma unroll
        for (int q = 0; q < 8; q++) hfma8p(u[q], pack2(n[q], n[q]), acc);
    }
    for (; p + 4 <= end; p += 4) {
        int s0 = __ldg(&csrc[p]);
        int s1 = __ldg(&csrc[p + 1]);
        int s2 = __ldg(&csrc[p + 2]);
        int s3 = __ldg(&csrc[p + 3]);
        float n0 = di * __ldg(&dinv[s0]);
        float n1 = di * __ldg(&dinv[s1]);
        float n2 = di * __ldg(&dinv[s2]);
        float n3 = di * __ldg(&dinv[s3]);
        uint4 u0 = __ldg(&hp[(size_t)s0 * 32 + lane]);
        uint4 u1 = __ldg(&hp[(size_t)s1 * 32 + lane]);
        uint4 u2 = __ldg(&hp[(size_t)s2 * 32 + lane]);
        uint4 u3 = __ldg(&hp[(size_t)s3 * 32 + lane]);
        hfma8p(u0, pack2(n0, n0), acc);
        hfma8p(u1, pack2(n1, n1), acc);
        hfma8p(u2, pack2(n2, n2), acc);
        hfma8p(u3, pack2(n3, n3), acc);
    }
    for (; p < end; p++) {
        int s0 = __ldg(&csrc[p]);
        float n0 = di * __ldg(&dinv[s0]);
        hfma8p(__ldg(&hp[(size_t)s0 * 32 + lane]), pack2(n0, n0), acc);
    }

    int c = lane * 8;
    float a[8];
#pragma unroll
    for (int q = 0; q < 4; q++) {
        float2 f = unpack2(acc[q]);
        a[2 * q] = f.x; a[2 * q + 1] = f.y;
    }
#pragma unroll
    for (int t = 0; t < 8; t++) {
        a[t] += __ldg(&bias[c + t]);
        a[t] = fmaxf(a[t], 0.f);
    }
    __half2 p0 = __floats2half2_rn(a[0], a[1]);
    __half2 p1 = __floats2half2_rn(a[2], a[3]);
    __half2 p2 = __floats2half2_rn(a[4], a[5]);
    __half2 p3 = __floats2half2_rn(a[6], a[7]);
    uint4 o;
    o.x = *(uint32_t*)&p0; o.y = *(uint32_t*)&p1;
    o.z = *(uint32_t*)&p2; o.w = *(uint32_t*)&p3;
    ((uint4*)out)[rowq] = o;
}

// ---------------------------------------------------------------------------
// CSR aggregation C=128 over PRESCALED rows (h' = h*dinv), one warp per node:
//   out[d] = dinv[d] * (h'[d] + sum_s h'[s]) + b2
// ---------------------------------------------------------------------------
__global__ __launch_bounds__(256) void k_agg128s(const int* __restrict__ rowptr,
                                                 const int* __restrict__ csrc,
                                                 const __half* __restrict__ h,
                                                 const float* __restrict__ dinv,
                                                 const float* __restrict__ bias,
                                                 __half* __restrict__ out) {
    int gtid = blockIdx.x * blockDim.x + threadIdx.x;
    int node = gtid >> 5;
    int lane = gtid & 31;
    if (node >= N_NODES) return;

    const uint2* hp = (const uint2*)h;
    size_t rowq = (size_t)node * 32 + lane;

    uint64_t acc[2] = {0, 0};
    hadd4p(__ldg(&hp[rowq]), acc);   // self term h'[d]

    int beg = rowptr[node];
    int end = rowptr[node + 1];
    int p = beg;
    for (; p + 8 <= end; p += 8) {
        int s[8];
        uint2 u[8];
#pragma unroll
        for (int q = 0; q < 8; q++) s[q] = __ldg(&csrc[p + q]);
#pragma unroll
        for (int q = 0; q < 8; q++) u[q] = __ldg(&hp[(size_t)s[q] * 32 + lane]);
#pragma unroll
        for (int q = 0; q < 8; q++) hadd4p(u[q], acc);
    }
    for (; p < end; p++) {
        int s0 = __ldg(&csrc[p]);
        hadd4p(__ldg(&hp[(size_t)s0 * 32 + lane]), acc);
    }

    float di = dinv[node];
    int c = lane * 4;
    float2 f0 = unpack2(acc[0]);
    float2 f1 = unpack2(acc[1]);
    f0.x = f0.x * di + __ldg(&bias[c + 0]);
    f0.y = f0.y * di + __ldg(&bias[c + 1]);
    f1.x = f1.x * di + __ldg(&bias[c + 2]);
    f1.y = f1.y * di + __ldg(&bias[c + 3]);

    __half2 p0 = __floats2half2_rn(f0.x, f0.y);
    __half2 p1 = __floats2half2_rn(f1.x, f1.y);
    uint2 o;
    o.x = *(uint32_t*)&p0; o.y = *(uint32_t*)&p1;
    ((uint2*)out)[rowq] = o;
}

// ---------------------------------------------------------------------------
// Decode: logits[e] = dot(zh[a], zh[b]); one edge per 8-lane octet
// (4 edges per warp). Each lane loads uint4 [sl] and [sl+8] per side —
// both fully coalesced 128B segments. 3-step shuffle reduce.
// ---------------------------------------------------------------------------
__global__ void k_decode(const void* __restrict__ peR,
                         const void* __restrict__ neR,
                         const __half* __restrict__ zh,
                         float* __restrict__ out) {
    int gtid = blockIdx.x * blockDim.x + threadIdx.x;
    int warp = gtid >> 5;
    int lane = gtid & 31;
    int oct  = lane >> 3;          // 0..3
    int sl   = lane & 7;           // sub-lane within octet
    int eg   = warp * 4 + oct;     // edge id, < 2E
    if (eg >= 2 * N_EDGES) return;
    const void* src = (eg < N_EDGES) ? peR : neR;
    int e = (eg < N_EDGES) ? eg : eg - N_EDGES;
    int a, b;
    if (g_is64) {
        a = (int)((const long long*)src)[e];
        b = (int)((const long long*)src)[N_EDGES + e];
    } else {
        a = ((const int*)src)[e];
        b = ((const int*)src)[N_EDGES + e];
    }
    const uint4* ra = (const uint4*)&zh[(size_t)a * H2];   // 16 uint4 per row
    const uint4* rb = (const uint4*)&zh[(size_t)b * H2];
    uint4 ua0 = __ldg(&ra[sl]);
    uint4 ub0 = __ldg(&rb[sl]);
    uint4 ua1 = __ldg(&ra[sl + 8]);
    uint4 ub1 = __ldg(&rb[sl + 8]);
    uint64_t acc0 = 0, acc1 = 0;
    ffma2(acc0, h2f2(ua0.x), h2f2(ub0.x));
    ffma2(acc1, h2f2(ua0.y), h2f2(ub0.y));
    ffma2(acc0, h2f2(ua0.z), h2f2(ub0.z));
    ffma2(acc1, h2f2(ua0.w), h2f2(ub0.w));
    ffma2(acc0, h2f2(ua1.x), h2f2(ub1.x));
    ffma2(acc1, h2f2(ua1.y), h2f2(ub1.y));
    ffma2(acc0, h2f2(ua1.z), h2f2(ub1.z));
    ffma2(acc1, h2f2(ua1.w), h2f2(ub1.w));
    float2 r0 = unpack2(acc0);
    float2 r1 = unpack2(acc1);
    float s = (r0.x + r0.y) + (r1.x + r1.y);
#pragma unroll
    for (int o = 4; o; o >>= 1) s += __shfl_xor_sync(0xFFFFFFFFu, s, o);
    if (sl == 0) out[eg] = s;
}

// ---------------------------------------------------------------------------
// Launch — GEMM1 forked onto a side stream to overlap the CSR build.
// ---------------------------------------------------------------------------
extern "C" void kernel_launch(void* const* d_in, const int* in_sizes, int n_in,
                              void* d_out, int out_size) {
    const float* x    = (const float*)d_in[0];
    const void*  trR  = d_in[1];
    const void*  peR  = d_in[2];
    const void*  neR  = d_in[3];
    const float* W1   = (const float*)d_in[4];
    const float* b1   = (const float*)d_in[5];
    const float* W2   = (const float*)d_in[6];
    const float* b2   = (const float*)d_in[7];
    float* out = (float*)d_out;

    __half *h1, *o1, *h2, *zh;
    float *dinv;
    int *deg, *rowptr, *cursor, *csrc, *bsum;
    cudaGetSymbolAddress((void**)&h1,     g_h1);
    cudaGetSymbolAddress((void**)&o1,     g_o1);
    cudaGetSymbolAddress((void**)&h2,     g_h2);
    cudaGetSymbolAddress((void**)&zh,     g_zh);
    cudaGetSymbolAddress((void**)&dinv,   g_dinv);
    cudaGetSymbolAddress((void**)&deg,    g_deg);
    cudaGetSymbolAddress((void**)&rowptr, g_rowptr);
    cudaGetSymbolAddress((void**)&cursor, g_cursor);
    cudaGetSymbolAddress((void**)&csrc,   g_csrc);
    cudaGetSymbolAddress((void**)&bsum,   g_bsum);

    static cudaStream_t s1 = nullptr;
    static cudaEvent_t  e_fork = nullptr, e_g1 = nullptr;
    if (s1 == nullptr) {
        cudaStreamCreateWithFlags(&s1, cudaStreamNonBlocking);
        cudaEventCreateWithFlags(&e_fork, cudaEventDisableTiming);
        cudaEventCreateWithFlags(&e_g1,   cudaEventDisableTiming);
    }

    // Fork GEMM1 (independent of all edge data) onto stream 1.
    cudaEventRecord(e_fork, 0);
    cudaStreamWaitEvent(s1, e_fork, 0);
    {
        dim3 grid(HIDDEN / GBN, (N_NODES + GBM - 1) / GBM);
        gemm_h16<false, false><<<grid, 256, 0, s1>>>(N_NODES, HIDDEN, N_FEAT,
                                                     x, W1, nullptr, h1);
    }
    cudaEventRecord(e_g1, s1);

    // Main: setup + parallel CSR build (deg kept zero across launches by scan1).
    k_detect<<<1, 256>>>((const unsigned int*)trR);
    k_deg_hist<<<(N_EDGES / 2 + 255) / 256, 256>>>(trR, deg);
    k_scan1<<<NB_SCAN, 256>>>(deg, rowptr, dinv, bsum);
    k_scan2<<<NB_SCAN, 256>>>(bsum, rowptr, cursor);
    k_scatter<<<(N_EDGES / 2 + 255) / 256, 256>>>(trR, cursor, csrc);

    // Join: agg1 needs both h1 (side) and CSR (main).
    cudaStreamWaitEvent(0, e_g1, 0);

    // o1 = relu(agg(h1) + b1)
    {
        long long threads = (long long)N_NODES * 32;
        k_agg256<<<(unsigned)((threads + 255) / 256), 256>>>(rowptr, csrc, h1, dinv, b1, o1);
    }

    // h2 = (o1 @ W2) * dinv[row]   (prescaled for agg2)
    {
        dim3 grid(H2 / GBN, (N_NODES + GBM - 1) / GBM);
        gemm_h16<true, true><<<grid, 256>>>(N_NODES, H2, HIDDEN, o1, W2, dinv, h2);
    }

    // zh = dinv[d]*(h2[d] + sum h2[s]) + b2
    {
        long long threads = (long long)N_NODES * 32;
        k_agg128s<<<(unsigned)((threads + 255) / 256), 256>>>(rowptr, csrc, h2, dinv, b2, zh);
    }

    // decode: one edge per 8-lane octet -> 2E/4 warps
    {
        long long threads = (long long)N_EDGES * 16;   // 2E * 8
        k_decode<<<(unsigned)((threads + 255) / 256), 256>>>(peR, neR, zh, out);
    }
}